// round 15
// baseline (speedup 1.0000x reference)
#include <cuda_runtime.h>
#include <cuda_fp16.h>
#include <cstdint>

#define NN   50000
#define FD   96
#define EMAX 800000
#define SCAN_BLK 512
#define SCAN_NB  ((NN + SCAN_BLK - 1) / SCAN_BLK)   // 98

// ---- device scratch: accessed ONLY from device code ----
__device__ __align__(16) float sg_msg1f[NN * 96];   // x@w1_l^T (fp32, gemm out)
__device__ __align__(16) float sg_root1[NN * 96];   // x@w1_r^T
__device__ __align__(16) float sg_hid[NN * 96];     // layer-1 out
__device__ __align__(16) float sg_msg2f[NN * 48];   // hid@w2_l^T (fp32, gemm out)
__device__ __align__(16) float sg_root2[NN * 48];   // hid@w2_r^T
__device__ __align__(16) float sg_wt1[FD * 192];    // k-major concat(w1_l,w1_r)
__device__ __align__(16) float sg_wt2[FD * 96];     // k-major concat(w2_l,w2_r)
__device__ __align__(16) __half sgh_msg1[NN * 96];  // fp16 copy for gather
__device__ __align__(16) __half sgh_msg2[NN * 48];
__device__ int sg_deg[NN];
__device__ int sg_rowptr[NN + 1];
__device__ int sg_cursor[NN];
__device__ int sg_adj[EMAX];
__device__ int sg_part[SCAN_NB];
__device__ int sg_is64;

__device__ __forceinline__ float* sg_sel(int w) {
    switch (w) {
        case 0: return sg_msg1f;
        case 1: return sg_root1;
        case 2: return sg_hid;
        case 3: return sg_msg2f;
        case 4: return sg_root2;
        case 5: return sg_wt1;
        default: return sg_wt2;
    }
}
__device__ __forceinline__ __half* sgh_sel(int w) {
    return (w == 0) ? sgh_msg1 : sgh_msg2;
}

// ---- init: zero deg + dtype sniff + weight transpose (fused) ----
__global__ void sgv15_init(const int* __restrict__ ei32, int n32,
                           const float* __restrict__ w1_l, const float* __restrict__ w1_r,
                           const float* __restrict__ w2_l, const float* __restrict__ w2_r) {
    int gid = blockIdx.x * blockDim.x + threadIdx.x;
    if (gid < NN) sg_deg[gid] = 0;
    if (gid == 0) {
        int nz = 0;
        int lim = (n32 < 1024) ? n32 : 1024;
        for (int j = 1; j < lim; j += 2) nz |= (ei32[j] != 0);
        sg_is64 = nz ? 0 : 1;
    }
    int stride = gridDim.x * blockDim.x;
    for (int i = gid; i < FD * 192 + FD * 96; i += stride) {
        if (i < FD * 192) {
            int k = i / 192, o = i % 192;
            sg_wt1[i] = (o < 96) ? w1_l[o * FD + k] : w1_r[(o - 96) * FD + k];
        } else {
            int j = i - FD * 192;
            int k = j / 96, o = j % 96;
            sg_wt2[j] = (o < 48) ? w2_l[o * FD + k] : w2_r[(o - 48) * FD + k];
        }
    }
}

__device__ __forceinline__ int sgv15_edge(const void* ei, int idx, int is64) {
    int v = is64 ? (int)((const long long*)ei)[idx] : ((const int*)ei)[idx];
    return min(max(v, 0), NN - 1);
}

__global__ void sgv15_count(const void* __restrict__ ei, int E) {
    int stride = gridDim.x * blockDim.x;
    int is64 = sg_is64;
    for (int e = blockIdx.x * blockDim.x + threadIdx.x; e < E; e += stride)
        atomicAdd(&sg_deg[sgv15_edge(ei, e + E, is64)], 1);
}

// ---- 2-phase scan ----
__global__ void __launch_bounds__(SCAN_BLK) sgv15_scan_a() {
    __shared__ int sm[SCAN_BLK];
    int t = threadIdx.x;
    int i = blockIdx.x * SCAN_BLK + t;
    sm[t] = (i < NN) ? sg_deg[i] : 0;
    __syncthreads();
    for (int off = SCAN_BLK / 2; off > 0; off >>= 1) {
        if (t < off) sm[t] += sm[t + off];
        __syncthreads();
    }
    if (t == 0) sg_part[blockIdx.x] = sm[0];
}

__global__ void __launch_bounds__(SCAN_BLK) sgv15_scan_c() {
    __shared__ int sm[SCAN_BLK];
    __shared__ int soff;
    int t = threadIdx.x;
    int bid = blockIdx.x;
    int pv = (t < bid) ? sg_part[t] : 0;    // SCAN_NB=98 < SCAN_BLK
    sm[t] = pv;
    __syncthreads();
    for (int off = SCAN_BLK / 2; off > 0; off >>= 1) {
        if (t < off) sm[t] += sm[t + off];
        __syncthreads();
    }
    if (t == 0) soff = sm[0];
    __syncthreads();
    int off0 = soff;
    int i = bid * SCAN_BLK + t;
    int v = (i < NN) ? sg_deg[i] : 0;
    sm[t] = v;
    __syncthreads();
    for (int off = 1; off < SCAN_BLK; off <<= 1) {
        int add = (t >= off) ? sm[t - off] : 0;
        __syncthreads();
        sm[t] += add;
        __syncthreads();
    }
    if (i < NN) {
        int excl = off0 + sm[t] - v;
        sg_rowptr[i] = excl;
        sg_cursor[i] = excl;
    }
    if (bid == SCAN_NB - 1 && t == SCAN_BLK - 1)
        sg_rowptr[NN] = off0 + sm[SCAN_BLK - 1];
}

__global__ void sgv15_bucket(const void* __restrict__ ei, int E) {
    int stride = gridDim.x * blockDim.x;
    int is64 = sg_is64;
    for (int e = blockIdx.x * blockDim.x + threadIdx.x; e < E; e += stride) {
        int d = sgv15_edge(ei, e + E, is64);
        int s = sgv15_edge(ei, e, is64);
        int p = atomicAdd(&sg_cursor[d], 1);
        sg_adj[p] = s;
    }
}

// ---- dual GEMM, k-major X tile: [Oa | Ob](row,:) = X(row,:) @ WT ----
// Per k per thread: 2x LDS.128 (8 row values) + 1x LDG.128 (4 w cols) + 32 FFMA.
template <int OUTT, int XSEL, int WSEL, int OA, int OB>
__global__ void __launch_bounds__(192) sgv15_gemm(const float* __restrict__ Xin) {
    const int TQ = OUTT / 4;        // 48 or 24
    const int TY = 192 / TQ;        // 4 or 8
    const int ROWS = TY * 8;        // 32 or 64
    const int XR = ROWS + 4;        // multiple of 4 -> LDS.128 alignment holds
    const int HALF = OUTT / 2;

    __shared__ __align__(16) float xs[FD * XR];   // 13.8 KB / 26.1 KB static

    const float* X = (XSEL < 0) ? Xin : sg_sel(XSEL);
    const float* WT = sg_sel(WSEL);
    float* Oa = sg_sel(OA);
    float* Ob = sg_sel(OB);

    int tid = threadIdx.x;
    int R0 = blockIdx.x * ROWS;

    // X tile transposed: xs[k][r]
    for (int i = tid; i < ROWS * (FD / 4); i += 192) {
        int r = i / (FD / 4), kc = i % (FD / 4);
        int row = R0 + r;
        float4 v = (row < NN) ? ((const float4*)(X + (size_t)row * FD))[kc]
                              : make_float4(0.f, 0.f, 0.f, 0.f);
        xs[(kc * 4 + 0) * XR + r] = v.x;
        xs[(kc * 4 + 1) * XR + r] = v.y;
        xs[(kc * 4 + 2) * XR + r] = v.z;
        xs[(kc * 4 + 3) * XR + r] = v.w;
    }
    __syncthreads();

    int tx = tid % TQ, ty = tid / TQ;
    int c0 = tx * 4, r0 = ty * 8;

    float acc[8][4];
#pragma unroll
    for (int i = 0; i < 8; i++)
#pragma unroll
        for (int j = 0; j < 4; j++) acc[i][j] = 0.f;

#pragma unroll 4
    for (int k = 0; k < FD; k++) {
        float4 w = *(const float4*)&WT[k * OUTT + c0];
        float4 xa = *(const float4*)&xs[k * XR + r0];
        float4 xb = *(const float4*)&xs[k * XR + r0 + 4];
        float xv[8] = {xa.x, xa.y, xa.z, xa.w, xb.x, xb.y, xb.z, xb.w};
#pragma unroll
        for (int i = 0; i < 8; i++) {
            acc[i][0] = fmaf(w.x, xv[i], acc[i][0]);
            acc[i][1] = fmaf(w.y, xv[i], acc[i][1]);
            acc[i][2] = fmaf(w.z, xv[i], acc[i][2]);
            acc[i][3] = fmaf(w.w, xv[i], acc[i][3]);
        }
    }

    float* Obase = (c0 < HALF) ? (Oa + c0) : (Ob + (c0 - HALF));
#pragma unroll
    for (int i = 0; i < 8; i++) {
        int row = R0 + r0 + i;
        if (row >= NN) break;
        *(float4*)&Obase[(size_t)row * HALF] =
            make_float4(acc[i][0], acc[i][1], acc[i][2], acc[i][3]);
    }
}

// ---- fp32 -> fp16 convert ----
template <int TOT, int FSEL, int HSEL>
__global__ void __launch_bounds__(256) sgv15_conv() {
    const float4* src = (const float4*)sg_sel(FSEL);
    uint2* dst = (uint2*)sgh_sel(HSEL);
    int stride = gridDim.x * blockDim.x;
    for (int i = blockIdx.x * blockDim.x + threadIdx.x; i < TOT / 4; i += stride) {
        float4 v = src[i];
        __half2 h0 = __floats2half2_rn(v.x, v.y);
        __half2 h1 = __floats2half2_rn(v.z, v.w);
        uint2 u;
        u.x = *(uint32_t*)&h0;
        u.y = *(uint32_t*)&h1;
        dst[i] = u;
    }
}

// ---- fused gather (fp16 msgs, uint2 lanes) + fp32 epilogue ----
template <int OUT, int RELU, int HSEL, int RSEL, int OSEL>
__global__ void __launch_bounds__(256) sgv15_gather(const float* __restrict__ bias,
                                                    float* __restrict__ Oext) {
    const int SUBW = (OUT == 96) ? 32 : 16;
    const int VQ = OUT / 4;
    int t = blockIdx.x * 256 + threadIdx.x;
    int node = t / SUBW;
    int sl = t % SUBW;
    if (node >= NN || sl >= VQ) return;

    const __half* Vh = sgh_sel(HSEL);
    const float* root = sg_sel(RSEL);
    float* O = (OSEL < 0) ? Oext : sg_sel(OSEL);

    int beg = sg_rowptr[node], end = sg_rowptr[node + 1];

    float4 a = make_float4(0.f, 0.f, 0.f, 0.f);
    float4 b = make_float4(0.f, 0.f, 0.f, 0.f);
    int j = beg;
    for (; j + 1 < end; j += 2) {
        uint2 u0 = *(const uint2*)&Vh[(size_t)sg_adj[j] * OUT + sl * 4];
        uint2 u1 = *(const uint2*)&Vh[(size_t)sg_adj[j + 1] * OUT + sl * 4];
        float2 f00 = __half22float2(*(__half2*)&u0.x);
        float2 f01 = __half22float2(*(__half2*)&u0.y);
        float2 f10 = __half22float2(*(__half2*)&u1.x);
        float2 f11 = __half22float2(*(__half2*)&u1.y);
        a.x += f00.x; a.y += f00.y; a.z += f01.x; a.w += f01.y;
        b.x += f10.x; b.y += f10.y; b.z += f11.x; b.w += f11.y;
    }
    if (j < end) {
        uint2 u0 = *(const uint2*)&Vh[(size_t)sg_adj[j] * OUT + sl * 4];
        float2 f00 = __half22float2(*(__half2*)&u0.x);
        float2 f01 = __half22float2(*(__half2*)&u0.y);
        a.x += f00.x; a.y += f00.y; a.z += f01.x; a.w += f01.y;
    }
    float inv = 1.f / fmaxf((float)(end - beg), 1.f);
    float4 rt = *(const float4*)&root[(size_t)node * OUT + sl * 4];
    float4 bb = *(const float4*)&bias[sl * 4];
    float4 v;
    v.x = (a.x + b.x) * inv + rt.x + bb.x;
    v.y = (a.y + b.y) * inv + rt.y + bb.y;
    v.z = (a.z + b.z) * inv + rt.z + bb.z;
    v.w = (a.w + b.w) * inv + rt.w + bb.w;
    if (RELU) {
        v.x = fmaxf(v.x, 0.f); v.y = fmaxf(v.y, 0.f);
        v.z = fmaxf(v.z, 0.f); v.w = fmaxf(v.w, 0.f);
    }
    *(float4*)&O[(size_t)node * OUT + sl * 4] = v;
}

extern "C" void kernel_launch(void* const* d_in, const int* in_sizes, int n_in,
                              void* d_out, int out_size) {
    const float* x    = (const float*)d_in[0];
    const void*  ei   = d_in[1];
    const float* w1_l = (const float*)d_in[2];
    const float* b1   = (const float*)d_in[3];
    const float* w1_r = (const float*)d_in[4];
    const float* w2_l = (const float*)d_in[5];
    const float* b2   = (const float*)d_in[6];
    const float* w2_r = (const float*)d_in[7];
    float*       out  = (float*)d_out;

    int E = in_sizes[1] / 2;
    if (E > EMAX) E = EMAX;

    const int g1_blocks = (NN + 31) / 32;
    const int g2_blocks = (NN + 63) / 64;
    const int ga96_blocks = (NN * 32 + 255) / 256;
    const int ga48_blocks = (NN * 16 + 255) / 256;

    // fork-join: CSR chain on a side stream, GEMM chain on the main stream
    cudaStream_t side;
    cudaStreamCreateWithFlags(&side, cudaStreamNonBlocking);
    cudaEvent_t evFork, evJoin;
    cudaEventCreateWithFlags(&evFork, cudaEventDisableTiming);
    cudaEventCreateWithFlags(&evJoin, cudaEventDisableTiming);

    sgv15_init<<<SCAN_NB, SCAN_BLK>>>((const int*)ei, in_sizes[1], w1_l, w1_r, w2_l, w2_r);
    cudaEventRecord(evFork, 0);
    cudaStreamWaitEvent(side, evFork, 0);

    // side branch: CSR build
    sgv15_count<<<1024, 256, 0, side>>>(ei, E);
    sgv15_scan_a<<<SCAN_NB, SCAN_BLK, 0, side>>>();
    sgv15_scan_c<<<SCAN_NB, SCAN_BLK, 0, side>>>();
    sgv15_bucket<<<1024, 256, 0, side>>>(ei, E);
    cudaEventRecord(evJoin, side);

    // main branch: layer-1 GEMM + fp16 convert
    sgv15_gemm<192, -1, 5, 0, 1><<<g1_blocks, 192>>>(x);
    sgv15_conv<NN * 96, 0, 0><<<1024, 256>>>();

    // join, then the serial tail
    cudaStreamWaitEvent(0, evJoin, 0);
    sgv15_gather<96, 1, 0, 1, 2><<<ga96_blocks, 256>>>(b1, nullptr);
    sgv15_gemm<96, 2, 6, 3, 4><<<g2_blocks, 192>>>(nullptr);
    sgv15_conv<NN * 48, 3, 1><<<512, 256>>>();
    sgv15_gather<48, 0, 1, 4, -1><<<ga48_blocks, 256>>>(b2, out);

    // destroy only when not capturing
    cudaStreamCaptureStatus st = cudaStreamCaptureStatusNone;
    cudaStreamIsCapturing(side, &st);
    if (st == cudaStreamCaptureStatusNone) {
        cudaStreamDestroy(side);
        cudaEventDestroy(evFork);
        cudaEventDestroy(evJoin);
    }
}

// round 16
// speedup vs baseline: 1.0181x; 1.0181x over previous
#include <cuda_runtime.h>
#include <cuda_fp16.h>
#include <cstdint>

#define NN   50000
#define FD   96
#define EMAX 800000
#define SCAN_BLK 512
#define SCAN_NB  ((NN + SCAN_BLK - 1) / SCAN_BLK)   // 98

// ---- device scratch: accessed ONLY from device code ----
__device__ __align__(16) float sg_root1[NN * 96];   // x@w1_r^T
__device__ __align__(16) float sg_hid[NN * 96];     // layer-1 out
__device__ __align__(16) float sg_root2[NN * 48];   // hid@w2_r^T
__device__ __align__(16) float sg_wt1[FD * 192];    // k-major concat(w1_l,w1_r)
__device__ __align__(16) float sg_wt2[FD * 96];     // k-major concat(w2_l,w2_r)
__device__ __align__(16) __half sgh_msg1[NN * 96];  // x@w1_l^T (fp16, gemm epi)
__device__ __align__(16) __half sgh_msg2[NN * 48];  // hid@w2_l^T (fp16, gemm epi)
__device__ int sg_deg[NN];
__device__ int sg_rowptr[NN + 1];
__device__ int sg_cursor[NN];
__device__ int sg_adj[EMAX];
__device__ int sg_part[SCAN_NB];
__device__ int sg_is64;

__device__ __forceinline__ float* sg_sel(int w) {
    switch (w) {
        case 0: return sg_root1;
        case 1: return sg_hid;
        case 2: return sg_root2;
        case 3: return sg_wt1;
        default: return sg_wt2;
    }
}
__device__ __forceinline__ __half* sgh_sel(int w) {
    return (w == 0) ? sgh_msg1 : sgh_msg2;
}

// ---- init: zero deg + dtype sniff + weight transpose (fused) ----
__global__ void sgv16_init(const int* __restrict__ ei32, int n32,
                           const float* __restrict__ w1_l, const float* __restrict__ w1_r,
                           const float* __restrict__ w2_l, const float* __restrict__ w2_r) {
    int gid = blockIdx.x * blockDim.x + threadIdx.x;
    if (gid < NN) sg_deg[gid] = 0;
    if (gid == 0) {
        int nz = 0;
        int lim = (n32 < 1024) ? n32 : 1024;
        for (int j = 1; j < lim; j += 2) nz |= (ei32[j] != 0);
        sg_is64 = nz ? 0 : 1;
    }
    int stride = gridDim.x * blockDim.x;
    for (int i = gid; i < FD * 192 + FD * 96; i += stride) {
        if (i < FD * 192) {
            int k = i / 192, o = i % 192;
            sg_wt1[i] = (o < 96) ? w1_l[o * FD + k] : w1_r[(o - 96) * FD + k];
        } else {
            int j = i - FD * 192;
            int k = j / 96, o = j % 96;
            sg_wt2[j] = (o < 48) ? w2_l[o * FD + k] : w2_r[(o - 48) * FD + k];
        }
    }
}

__device__ __forceinline__ int sgv16_edge(const void* ei, int idx, int is64) {
    int v = is64 ? (int)((const long long*)ei)[idx] : ((const int*)ei)[idx];
    return min(max(v, 0), NN - 1);
}

__global__ void sgv16_count(const void* __restrict__ ei, int E) {
    int stride = gridDim.x * blockDim.x;
    int is64 = sg_is64;
    for (int e = blockIdx.x * blockDim.x + threadIdx.x; e < E; e += stride)
        atomicAdd(&sg_deg[sgv16_edge(ei, e + E, is64)], 1);
}

// ---- 2-phase scan ----
__global__ void __launch_bounds__(SCAN_BLK) sgv16_scan_a() {
    __shared__ int sm[SCAN_BLK];
    int t = threadIdx.x;
    int i = blockIdx.x * SCAN_BLK + t;
    sm[t] = (i < NN) ? sg_deg[i] : 0;
    __syncthreads();
    for (int off = SCAN_BLK / 2; off > 0; off >>= 1) {
        if (t < off) sm[t] += sm[t + off];
        __syncthreads();
    }
    if (t == 0) sg_part[blockIdx.x] = sm[0];
}

__global__ void __launch_bounds__(SCAN_BLK) sgv16_scan_c() {
    __shared__ int sm[SCAN_BLK];
    __shared__ int soff;
    int t = threadIdx.x;
    int bid = blockIdx.x;
    int pv = (t < bid) ? sg_part[t] : 0;    // SCAN_NB=98 < SCAN_BLK
    sm[t] = pv;
    __syncthreads();
    for (int off = SCAN_BLK / 2; off > 0; off >>= 1) {
        if (t < off) sm[t] += sm[t + off];
        __syncthreads();
    }
    if (t == 0) soff = sm[0];
    __syncthreads();
    int off0 = soff;
    int i = bid * SCAN_BLK + t;
    int v = (i < NN) ? sg_deg[i] : 0;
    sm[t] = v;
    __syncthreads();
    for (int off = 1; off < SCAN_BLK; off <<= 1) {
        int add = (t >= off) ? sm[t - off] : 0;
        __syncthreads();
        sm[t] += add;
        __syncthreads();
    }
    if (i < NN) {
        int excl = off0 + sm[t] - v;
        sg_rowptr[i] = excl;
        sg_cursor[i] = excl;
    }
    if (bid == SCAN_NB - 1 && t == SCAN_BLK - 1)
        sg_rowptr[NN] = off0 + sm[SCAN_BLK - 1];
}

__global__ void sgv16_bucket(const void* __restrict__ ei, int E) {
    int stride = gridDim.x * blockDim.x;
    int is64 = sg_is64;
    for (int e = blockIdx.x * blockDim.x + threadIdx.x; e < E; e += stride) {
        int d = sgv16_edge(ei, e + E, is64);
        int s = sgv16_edge(ei, e, is64);
        int p = atomicAdd(&sg_cursor[d], 1);
        sg_adj[p] = s;
    }
}

// ---- dual GEMM (R8 mainloop) + fused fp16 msg epilogue ----
// [Msg(fp16) | Root(fp32)](row,:) = X(row,:) @ WT (k-major [FD][OUTT])
template <int OUTT, int XSEL, int WSEL, int HSEL, int RSEL>
__global__ void __launch_bounds__(192) sgv16_gemm(const float* __restrict__ Xin) {
    const int TQ = OUTT / 4;        // 48 or 24
    const int TY = 192 / TQ;        // 4 or 8
    const int ROWS = TY * 8;        // 32 or 64
    const int XP = FD + 4;          // 100
    const int HALF = OUTT / 2;

    __shared__ __align__(16) float xs[ROWS * XP];

    const float* X = (XSEL < 0) ? Xin : sg_sel(XSEL);
    const float* WT = sg_sel(WSEL);
    __half* H = sgh_sel(HSEL);
    float* R = sg_sel(RSEL);

    int tid = threadIdx.x;
    int R0 = blockIdx.x * ROWS;

    for (int i = tid; i < ROWS * (FD / 4); i += 192) {
        int r = i / (FD / 4), kc = i % (FD / 4);
        int row = R0 + r;
        float4 v = (row < NN) ? ((const float4*)(X + (size_t)row * FD))[kc]
                              : make_float4(0.f, 0.f, 0.f, 0.f);
        *(float4*)&xs[r * XP + kc * 4] = v;
    }
    __syncthreads();

    int tx = tid % TQ, ty = tid / TQ;
    int c0 = tx * 4, r0 = ty * 8;

    float acc[8][4];
#pragma unroll
    for (int i = 0; i < 8; i++)
#pragma unroll
        for (int j = 0; j < 4; j++) acc[i][j] = 0.f;

#pragma unroll 4
    for (int k = 0; k < FD; k++) {
        float4 w = *(const float4*)&WT[k * OUTT + c0];
#pragma unroll
        for (int i = 0; i < 8; i++) {
            float xv = xs[(r0 + i) * XP + k];
            acc[i][0] = fmaf(w.x, xv, acc[i][0]);
            acc[i][1] = fmaf(w.y, xv, acc[i][1]);
            acc[i][2] = fmaf(w.z, xv, acc[i][2]);
            acc[i][3] = fmaf(w.w, xv, acc[i][3]);
        }
    }

    if (c0 < HALF) {
#pragma unroll
        for (int i = 0; i < 8; i++) {
            int row = R0 + r0 + i;
            if (row >= NN) break;
            __half2 h0 = __floats2half2_rn(acc[i][0], acc[i][1]);
            __half2 h1 = __floats2half2_rn(acc[i][2], acc[i][3]);
            uint2 u;
            u.x = *(uint32_t*)&h0;
            u.y = *(uint32_t*)&h1;
            *(uint2*)&H[(size_t)row * HALF + c0] = u;
        }
    } else {
#pragma unroll
        for (int i = 0; i < 8; i++) {
            int row = R0 + r0 + i;
            if (row >= NN) break;
            *(float4*)&R[(size_t)row * HALF + (c0 - HALF)] =
                make_float4(acc[i][0], acc[i][1], acc[i][2], acc[i][3]);
        }
    }
}

// ---- fused gather (fp16 msgs, uint2 lanes) + fp32 epilogue ----
template <int OUT, int RELU, int HSEL, int RSEL, int OSEL>
__global__ void __launch_bounds__(256) sgv16_gather(const float* __restrict__ bias,
                                                    float* __restrict__ Oext) {
    const int SUBW = (OUT == 96) ? 32 : 16;
    const int VQ = OUT / 4;
    int t = blockIdx.x * 256 + threadIdx.x;
    int node = t / SUBW;
    int sl = t % SUBW;
    if (node >= NN || sl >= VQ) return;

    const __half* Vh = sgh_sel(HSEL);
    const float* root = sg_sel(RSEL);
    float* O = (OSEL < 0) ? Oext : sg_sel(OSEL);

    int beg = sg_rowptr[node], end = sg_rowptr[node + 1];

    float4 a = make_float4(0.f, 0.f, 0.f, 0.f);
    float4 b = make_float4(0.f, 0.f, 0.f, 0.f);
    int j = beg;
    for (; j + 1 < end; j += 2) {
        uint2 u0 = *(const uint2*)&Vh[(size_t)sg_adj[j] * OUT + sl * 4];
        uint2 u1 = *(const uint2*)&Vh[(size_t)sg_adj[j + 1] * OUT + sl * 4];
        float2 f00 = __half22float2(*(__half2*)&u0.x);
        float2 f01 = __half22float2(*(__half2*)&u0.y);
        float2 f10 = __half22float2(*(__half2*)&u1.x);
        float2 f11 = __half22float2(*(__half2*)&u1.y);
        a.x += f00.x; a.y += f00.y; a.z += f01.x; a.w += f01.y;
        b.x += f10.x; b.y += f10.y; b.z += f11.x; b.w += f11.y;
    }
    if (j < end) {
        uint2 u0 = *(const uint2*)&Vh[(size_t)sg_adj[j] * OUT + sl * 4];
        float2 f00 = __half22float2(*(__half2*)&u0.x);
        float2 f01 = __half22float2(*(__half2*)&u0.y);
        a.x += f00.x; a.y += f00.y; a.z += f01.x; a.w += f01.y;
    }
    float inv = 1.f / fmaxf((float)(end - beg), 1.f);
    float4 rt = *(const float4*)&root[(size_t)node * OUT + sl * 4];
    float4 bb = *(const float4*)&bias[sl * 4];
    float4 v;
    v.x = (a.x + b.x) * inv + rt.x + bb.x;
    v.y = (a.y + b.y) * inv + rt.y + bb.y;
    v.z = (a.z + b.z) * inv + rt.z + bb.z;
    v.w = (a.w + b.w) * inv + rt.w + bb.w;
    if (RELU) {
        v.x = fmaxf(v.x, 0.f); v.y = fmaxf(v.y, 0.f);
        v.z = fmaxf(v.z, 0.f); v.w = fmaxf(v.w, 0.f);
    }
    *(float4*)&O[(size_t)node * OUT + sl * 4] = v;
}

extern "C" void kernel_launch(void* const* d_in, const int* in_sizes, int n_in,
                              void* d_out, int out_size) {
    const float* x    = (const float*)d_in[0];
    const void*  ei   = d_in[1];
    const float* w1_l = (const float*)d_in[2];
    const float* b1   = (const float*)d_in[3];
    const float* w1_r = (const float*)d_in[4];
    const float* w2_l = (const float*)d_in[5];
    const float* b2   = (const float*)d_in[6];
    const float* w2_r = (const float*)d_in[7];
    float*       out  = (float*)d_out;

    int E = in_sizes[1] / 2;
    if (E > EMAX) E = EMAX;

    const int g1_blocks = (NN + 31) / 32;
    const int g2_blocks = (NN + 63) / 64;
    const int ga96_blocks = (NN * 32 + 255) / 256;
    const int ga48_blocks = (NN * 16 + 255) / 256;

    // fork-join: CSR chain on a side stream, GEMM chain on the main stream
    cudaStream_t side;
    cudaStreamCreateWithFlags(&side, cudaStreamNonBlocking);
    cudaEvent_t evFork, evJoin;
    cudaEventCreateWithFlags(&evFork, cudaEventDisableTiming);
    cudaEventCreateWithFlags(&evJoin, cudaEventDisableTiming);

    sgv16_init<<<SCAN_NB, SCAN_BLK>>>((const int*)ei, in_sizes[1], w1_l, w1_r, w2_l, w2_r);
    cudaEventRecord(evFork, 0);
    cudaStreamWaitEvent(side, evFork, 0);

    // side branch: CSR build
    sgv16_count<<<1024, 256, 0, side>>>(ei, E);
    sgv16_scan_a<<<SCAN_NB, SCAN_BLK, 0, side>>>();
    sgv16_scan_c<<<SCAN_NB, SCAN_BLK, 0, side>>>();
    sgv16_bucket<<<1024, 256, 0, side>>>(ei, E);
    cudaEventRecord(evJoin, side);

    // main branch: layer-1 GEMM with fused fp16 msg epilogue
    sgv16_gemm<192, -1, 3, 0, 0><<<g1_blocks, 192>>>(x);

    // join, then the serial tail
    cudaStreamWaitEvent(0, evJoin, 0);
    sgv16_gather<96, 1, 0, 0, 1><<<ga96_blocks, 256>>>(b1, nullptr);
    sgv16_gemm<96, 1, 4, 1, 2><<<g2_blocks, 192>>>(nullptr);
    sgv16_gather<48, 0, 1, 2, -1><<<ga48_blocks, 256>>>(b2, out);

    // destroy only when not capturing
    cudaStreamCaptureStatus st = cudaStreamCaptureStatusNone;
    cudaStreamIsCapturing(side, &st);
    if (st == cudaStreamCaptureStatusNone) {
        cudaStreamDestroy(side);
        cudaEventDestroy(evFork);
        cudaEventDestroy(evJoin);
    }
}

// round 17
// speedup vs baseline: 1.0503x; 1.0316x over previous
#include <cuda_runtime.h>
#include <cuda_fp16.h>
#include <cstdint>

#define NN   50000
#define FD   96
#define EMAX 800000
#define SCAN_BLK 512
#define SCAN_NB  ((NN + SCAN_BLK - 1) / SCAN_BLK)   // 98

// ---- device scratch: accessed ONLY from device code ----
__device__ __align__(16) float sg_root1[NN * 96];   // x@w1_r^T
__device__ __align__(16) float sg_hid[NN * 96];     // layer-1 out
__device__ __align__(16) float sg_root2[NN * 48];   // hid@w2_r^T
__device__ __align__(16) float sg_wtm1[FD * 96];    // k-major w1_l
__device__ __align__(16) float sg_wtr1[FD * 96];    // k-major w1_r
__device__ __align__(16) float sg_wtm2[FD * 48];    // k-major w2_l
__device__ __align__(16) float sg_wtr2[FD * 48];    // k-major w2_r
__device__ __align__(16) __half sgh_msg1[NN * 96];  // x@w1_l^T (fp16)
__device__ __align__(16) __half sgh_msg2[NN * 48];  // hid@w2_l^T (fp16)
__device__ int sg_deg[NN];
__device__ int sg_rowptr[NN + 1];
__device__ int sg_cursor[NN];
__device__ int sg_adj[EMAX];
__device__ int sg_part[SCAN_NB];
__device__ int sg_is64;

__device__ __forceinline__ float* sg_sel(int w) {
    switch (w) {
        case 0: return sg_root1;
        case 1: return sg_hid;
        case 2: return sg_root2;
        case 3: return sg_wtm1;
        case 4: return sg_wtr1;
        case 5: return sg_wtm2;
        default: return sg_wtr2;
    }
}
__device__ __forceinline__ __half* sgh_sel(int w) {
    return (w == 0) ? sgh_msg1 : sgh_msg2;
}

// ---- init: zero deg + dtype sniff + weight transposes (fused) ----
__global__ void sgv17_init(const int* __restrict__ ei32, int n32,
                           const float* __restrict__ w1_l, const float* __restrict__ w1_r,
                           const float* __restrict__ w2_l, const float* __restrict__ w2_r) {
    int gid = blockIdx.x * blockDim.x + threadIdx.x;
    if (gid < NN) sg_deg[gid] = 0;
    if (gid == 0) {
        int nz = 0;
        int lim = (n32 < 1024) ? n32 : 1024;
        for (int j = 1; j < lim; j += 2) nz |= (ei32[j] != 0);
        sg_is64 = nz ? 0 : 1;
    }
    int stride = gridDim.x * blockDim.x;
    const int T96 = FD * 96, T48 = FD * 48;
    for (int i = gid; i < T96 * 2 + T48 * 2; i += stride) {
        if (i < T96) {
            int k = i / 96, o = i % 96;
            sg_wtm1[i] = w1_l[o * FD + k];
            sg_wtr1[i] = w1_r[o * FD + k];
        } else if (i < T96 * 2) {
            // second pass slot reserved (loop covers both via first branch)
        } else if (i < T96 * 2 + T48) {
            int j = i - T96 * 2;
            int k = j / 48, o = j % 48;
            sg_wtm2[j] = w2_l[o * FD + k];
            sg_wtr2[j] = w2_r[o * FD + k];
        }
    }
}

__device__ __forceinline__ int sgv17_edge(const void* ei, int idx, int is64) {
    int v = is64 ? (int)((const long long*)ei)[idx] : ((const int*)ei)[idx];
    return min(max(v, 0), NN - 1);
}

__global__ void sgv17_count(const void* __restrict__ ei, int E) {
    int stride = gridDim.x * blockDim.x;
    int is64 = sg_is64;
    for (int e = blockIdx.x * blockDim.x + threadIdx.x; e < E; e += stride)
        atomicAdd(&sg_deg[sgv17_edge(ei, e + E, is64)], 1);
}

// ---- 2-phase scan ----
__global__ void __launch_bounds__(SCAN_BLK) sgv17_scan_a() {
    __shared__ int sm[SCAN_BLK];
    int t = threadIdx.x;
    int i = blockIdx.x * SCAN_BLK + t;
    sm[t] = (i < NN) ? sg_deg[i] : 0;
    __syncthreads();
    for (int off = SCAN_BLK / 2; off > 0; off >>= 1) {
        if (t < off) sm[t] += sm[t + off];
        __syncthreads();
    }
    if (t == 0) sg_part[blockIdx.x] = sm[0];
}

__global__ void __launch_bounds__(SCAN_BLK) sgv17_scan_c() {
    __shared__ int sm[SCAN_BLK];
    __shared__ int soff;
    int t = threadIdx.x;
    int bid = blockIdx.x;
    int pv = (t < bid) ? sg_part[t] : 0;
    sm[t] = pv;
    __syncthreads();
    for (int off = SCAN_BLK / 2; off > 0; off >>= 1) {
        if (t < off) sm[t] += sm[t + off];
        __syncthreads();
    }
    if (t == 0) soff = sm[0];
    __syncthreads();
    int off0 = soff;
    int i = bid * SCAN_BLK + t;
    int v = (i < NN) ? sg_deg[i] : 0;
    sm[t] = v;
    __syncthreads();
    for (int off = 1; off < SCAN_BLK; off <<= 1) {
        int add = (t >= off) ? sm[t - off] : 0;
        __syncthreads();
        sm[t] += add;
        __syncthreads();
    }
    if (i < NN) {
        int excl = off0 + sm[t] - v;
        sg_rowptr[i] = excl;
        sg_cursor[i] = excl;
    }
    if (bid == SCAN_NB - 1 && t == SCAN_BLK - 1)
        sg_rowptr[NN] = off0 + sm[SCAN_BLK - 1];
}

__global__ void sgv17_bucket(const void* __restrict__ ei, int E) {
    int stride = gridDim.x * blockDim.x;
    int is64 = sg_is64;
    for (int e = blockIdx.x * blockDim.x + threadIdx.x; e < E; e += stride) {
        int d = sgv17_edge(ei, e + E, is64);
        int s = sgv17_edge(ei, e, is64);
        int p = atomicAdd(&sg_cursor[d], 1);
        sg_adj[p] = s;
    }
}

// ---- single-output GEMM (R8 mainloop, uniform epilogue) ----
// O(row, 0..OUTT) = X(row,:) @ WT (k-major [FD][OUTT]).
// RT rows x 4 cols per thread; 192 threads; ROWS = (192/(OUTT/4))*RT.
// FP16OUT: 0 -> float4 stores to sg_sel(OSEL); 1 -> uint2 fp16 stores to sgh_sel(OSEL).
template <int OUTT, int RT, int XSEL, int WSEL, int FP16OUT, int OSEL>
__global__ void __launch_bounds__(192) sgv17_gemm(const float* __restrict__ Xin) {
    const int TQ = OUTT / 4;
    const int TY = 192 / TQ;
    const int ROWS = TY * RT;       // 64 for both configs
    const int XP = FD + 4;          // 100

    __shared__ __align__(16) float xs[ROWS * XP];   // 25.6 KB static

    const float* X = (XSEL < 0) ? Xin : sg_sel(XSEL);
    const float* WT = sg_sel(WSEL);

    int tid = threadIdx.x;
    int R0 = blockIdx.x * ROWS;

    for (int i = tid; i < ROWS * (FD / 4); i += 192) {
        int r = i / (FD / 4), kc = i % (FD / 4);
        int row = R0 + r;
        float4 v = (row < NN) ? ((const float4*)(X + (size_t)row * FD))[kc]
                              : make_float4(0.f, 0.f, 0.f, 0.f);
        *(float4*)&xs[r * XP + kc * 4] = v;
    }
    __syncthreads();

    int tx = tid % TQ, ty = tid / TQ;
    int c0 = tx * 4, r0 = ty * RT;

    float acc[RT][4];
#pragma unroll
    for (int i = 0; i < RT; i++)
#pragma unroll
        for (int j = 0; j < 4; j++) acc[i][j] = 0.f;

#pragma unroll 4
    for (int k = 0; k < FD; k++) {
        float4 w = *(const float4*)&WT[k * OUTT + c0];
#pragma unroll
        for (int i = 0; i < RT; i++) {
            float xv = xs[(r0 + i) * XP + k];
            acc[i][0] = fmaf(w.x, xv, acc[i][0]);
            acc[i][1] = fmaf(w.y, xv, acc[i][1]);
            acc[i][2] = fmaf(w.z, xv, acc[i][2]);
            acc[i][3] = fmaf(w.w, xv, acc[i][3]);
        }
    }

    if (FP16OUT) {
        __half* H = sgh_sel(OSEL);
#pragma unroll
        for (int i = 0; i < RT; i++) {
            int row = R0 + r0 + i;
            if (row >= NN) break;
            __half2 h0 = __floats2half2_rn(acc[i][0], acc[i][1]);
            __half2 h1 = __floats2half2_rn(acc[i][2], acc[i][3]);
            uint2 u;
            u.x = *(uint32_t*)&h0;
            u.y = *(uint32_t*)&h1;
            *(uint2*)&H[(size_t)row * OUTT + c0] = u;
        }
    } else {
        float* O = sg_sel(OSEL);
#pragma unroll
        for (int i = 0; i < RT; i++) {
            int row = R0 + r0 + i;
            if (row >= NN) break;
            *(float4*)&O[(size_t)row * OUTT + c0] =
                make_float4(acc[i][0], acc[i][1], acc[i][2], acc[i][3]);
        }
    }
}

// ---- fused gather (fp16 msgs, uint2 lanes) + fp32 epilogue ----
template <int OUT, int RELU, int HSEL, int RSEL, int OSEL>
__global__ void __launch_bounds__(256) sgv17_gather(const float* __restrict__ bias,
                                                    float* __restrict__ Oext) {
    const int SUBW = (OUT == 96) ? 32 : 16;
    const int VQ = OUT / 4;
    int t = blockIdx.x * 256 + threadIdx.x;
    int node = t / SUBW;
    int sl = t % SUBW;
    if (node >= NN || sl >= VQ) return;

    const __half* Vh = sgh_sel(HSEL);
    const float* root = sg_sel(RSEL);
    float* O = (OSEL < 0) ? Oext : sg_sel(OSEL);

    int beg = sg_rowptr[node], end = sg_rowptr[node + 1];

    float4 a = make_float4(0.f, 0.f, 0.f, 0.f);
    float4 b = make_float4(0.f, 0.f, 0.f, 0.f);
    int j = beg;
    for (; j + 1 < end; j += 2) {
        uint2 u0 = *(const uint2*)&Vh[(size_t)sg_adj[j] * OUT + sl * 4];
        uint2 u1 = *(const uint2*)&Vh[(size_t)sg_adj[j + 1] * OUT + sl * 4];
        float2 f00 = __half22float2(*(__half2*)&u0.x);
        float2 f01 = __half22float2(*(__half2*)&u0.y);
        float2 f10 = __half22float2(*(__half2*)&u1.x);
        float2 f11 = __half22float2(*(__half2*)&u1.y);
        a.x += f00.x; a.y += f00.y; a.z += f01.x; a.w += f01.y;
        b.x += f10.x; b.y += f10.y; b.z += f11.x; b.w += f11.y;
    }
    if (j < end) {
        uint2 u0 = *(const uint2*)&Vh[(size_t)sg_adj[j] * OUT + sl * 4];
        float2 f00 = __half22float2(*(__half2*)&u0.x);
        float2 f01 = __half22float2(*(__half2*)&u0.y);
        a.x += f00.x; a.y += f00.y; a.z += f01.x; a.w += f01.y;
    }
    float inv = 1.f / fmaxf((float)(end - beg), 1.f);
    float4 rt = *(const float4*)&root[(size_t)node * OUT + sl * 4];
    float4 bb = *(const float4*)&bias[sl * 4];
    float4 v;
    v.x = (a.x + b.x) * inv + rt.x + bb.x;
    v.y = (a.y + b.y) * inv + rt.y + bb.y;
    v.z = (a.z + b.z) * inv + rt.z + bb.z;
    v.w = (a.w + b.w) * inv + rt.w + bb.w;
    if (RELU) {
        v.x = fmaxf(v.x, 0.f); v.y = fmaxf(v.y, 0.f);
        v.z = fmaxf(v.z, 0.f); v.w = fmaxf(v.w, 0.f);
    }
    *(float4*)&O[(size_t)node * OUT + sl * 4] = v;
}

extern "C" void kernel_launch(void* const* d_in, const int* in_sizes, int n_in,
                              void* d_out, int out_size) {
    const float* x    = (const float*)d_in[0];
    const void*  ei   = d_in[1];
    const float* w1_l = (const float*)d_in[2];
    const float* b1   = (const float*)d_in[3];
    const float* w1_r = (const float*)d_in[4];
    const float* w2_l = (const float*)d_in[5];
    const float* b2   = (const float*)d_in[6];
    const float* w2_r = (const float*)d_in[7];
    float*       out  = (float*)d_out;

    int E = in_sizes[1] / 2;
    if (E > EMAX) E = EMAX;

    const int g96_blocks = (NN + 63) / 64;           // OUTT=96, RT=8 -> ROWS=64
    const int g48_blocks = (NN + 63) / 64;           // OUTT=48, RT=4 -> ROWS=64
    const int ga96_blocks = (NN * 32 + 255) / 256;
    const int ga48_blocks = (NN * 16 + 255) / 256;

    // fork-join: CSR chain on a side stream, GEMM chain on the main stream
    cudaStream_t side;
    cudaStreamCreateWithFlags(&side, cudaStreamNonBlocking);
    cudaEvent_t evFork, evJoin;
    cudaEventCreateWithFlags(&evFork, cudaEventDisableTiming);
    cudaEventCreateWithFlags(&evJoin, cudaEventDisableTiming);

    sgv17_init<<<SCAN_NB, SCAN_BLK>>>((const int*)ei, in_sizes[1], w1_l, w1_r, w2_l, w2_r);
    cudaEventRecord(evFork, 0);
    cudaStreamWaitEvent(side, evFork, 0);

    // side branch: CSR build
    sgv17_count<<<1024, 256, 0, side>>>(ei, E);
    sgv17_scan_a<<<SCAN_NB, SCAN_BLK, 0, side>>>();
    sgv17_scan_c<<<SCAN_NB, SCAN_BLK, 0, side>>>();
    sgv17_bucket<<<1024, 256, 0, side>>>(ei, E);
    cudaEventRecord(evJoin, side);

    // main branch: layer-1 msg GEMM (fp16 out) + root GEMM (fp32 out)
    sgv17_gemm<96, 8, -1, 3, 1, 0><<<g96_blocks, 192>>>(x);   // msg1 -> sgh_msg1
    sgv17_gemm<96, 8, -1, 4, 0, 0><<<g96_blocks, 192>>>(x);   // root1 -> sg_root1

    // join, then serial tail
    cudaStreamWaitEvent(0, evJoin, 0);
    sgv17_gather<96, 1, 0, 0, 1><<<ga96_blocks, 256>>>(b1, nullptr);
    sgv17_gemm<48, 4, 1, 5, 1, 1><<<g48_blocks, 192>>>(nullptr);  // msg2 -> sgh_msg2
    sgv17_gemm<48, 4, 1, 6, 0, 2><<<g48_blocks, 192>>>(nullptr);  // root2 -> sg_root2
    sgv17_gather<48, 0, 1, 2, -1><<<ga48_blocks, 256>>>(b2, out);

    // destroy only when not capturing
    cudaStreamCaptureStatus st = cudaStreamCaptureStatusNone;
    cudaStreamIsCapturing(side, &st);
    if (st == cudaStreamCaptureStatusNone) {
        cudaStreamDestroy(side);
        cudaEventDestroy(evFork);
        cudaEventDestroy(evJoin);
    }
}